// round 7
// baseline (speedup 1.0000x reference)
#include <cuda_runtime.h>
#include <math.h>

#define IMG 96
#define NT  256

// ---- smem layout (float word offsets) ----
// xs_dup: 32 ch x 4 rows x 36 dup-cols (float2), ch stride 292 (==4 mod 32), row stride 72
#define O_XS   0
#define XS_CST 292
#define XS_RST 72
#define O_PHI  9344                 // phi chunk: 36 k-rows x 64 d
#define O_HS   11648                // h: 64 px x 66
#define HS_ST  66
#define O_ST   15872                // stats: 64 x 8
#define O_PROJ 16384
#define O_PBV  16448
#define O_FC1W 16512
#define O_FC1B 16832
#define O_PHIB 16896
#define O_ALB  17184
#define O_BNI  17248
#define O_BNM  17312
#define O_BNB  17376
#define SMEM_F 17440                // 69760 bytes -> 3 blocks/SM

#define PK2(d, lo, hi) asm("mov.b64 %0, {%1, %2};" : "=l"(d) : "r"(lo), "r"(hi))
#define UPK2(lo, hi, v) asm("mov.b64 {%0, %1}, %2;" : "=r"(lo), "=r"(hi) : "l"(v))
#define FMA2(d, a, b) asm("fma.rn.f32x2 %0, %1, %2, %3;" : "=l"(d) : "l"(a), "l"(b), "l"(d))

__global__ __launch_bounds__(NT, 3) void sac_kernel(
    const float* __restrict__ x,       const float* __restrict__ fc1_w,
    const float* __restrict__ fc1_b,   const float* __restrict__ alpha_w,
    const float* __restrict__ alpha_b, const float* __restrict__ phi_w,
    const float* __restrict__ phi_b,   const float* __restrict__ bn_g,
    const float* __restrict__ bn_b,    const float* __restrict__ bn_m,
    const float* __restrict__ bn_v,    float* __restrict__ out)
{
    extern __shared__ float sm[];
    const int t  = threadIdx.x;
    const int jt = blockIdx.x;          // 3 col tiles of 32
    const int it = blockIdx.y;          // 48 row tiles of 2
    const int bz = blockIdx.z;
    const int j0 = jt * 32;

    // ---------------- Phase 0: stage ----------------
    // xs_dup: value stored twice as float2
    for (int idx = t; idx < 32 * 4 * 34; idx += NT) {
        int c = idx / 136, rem = idx - c * 136;
        int r = rem / 34,  cc = rem - r * 34;
        int gr = it * 2 - 1 + r, gc = j0 - 1 + cc;
        float v = 0.f;
        if ((unsigned)gr < IMG && (unsigned)gc < IMG)
            v = x[((bz * 32 + c) * IMG + gr) * IMG + gc];
        float2* p = (float2*)(sm + O_XS + c * XS_CST + r * XS_RST + cc * 2);
        *p = make_float2(v, v);
    }
    for (int idx = t; idx < 320; idx += NT) sm[O_FC1W + idx] = fc1_w[idx];
    for (int idx = t; idx < 288; idx += NT) sm[O_PHIB + idx] = phi_b[idx];
    if (t < 64) {
        sm[O_FC1B + t] = fc1_b[t];
        sm[O_ALB  + t] = alpha_b[t];
        sm[O_BNI  + t] = bn_g[t] * rsqrtf(bn_v[t] + 1e-5f);
        sm[O_BNM  + t] = bn_m[t];
        sm[O_BNB  + t] = bn_b[t];
    }
    __syncthreads();

    // ---------------- Phase A: stats, 16 thr/px, 4 passes of 16 px ----------------
    {
        const int sub = t & 15, pxi = t >> 4;
        #pragma unroll 1
        for (int p4 = 0; p4 < 4; p4++) {
            const int pxl = p4 * 16 + pxi;
            const int rr = pxl >> 5, ca = pxl & 31;
            float v[18];
            float s0 = 0.f, mn = 3.4e38f, mx = -3.4e38f, pb = 0.f;
            #pragma unroll
            for (int cc = 0; cc < 2; cc++) {
                const int c = sub + cc * 16;
                const float* xb = sm + O_XS + c * XS_CST + rr * XS_RST + ca * 2;
                const float* pbb = sm + O_PHIB + c * 9;
                #pragma unroll
                for (int kh = 0; kh < 3; kh++)
                    #pragma unroll
                    for (int kw = 0; kw < 3; kw++) {
                        float val = xb[kh * XS_RST + kw * 2];
                        v[cc * 9 + kh * 3 + kw] = val;
                        s0 += val;
                        mn = fminf(mn, val);
                        mx = fmaxf(mx, val);
                        pb += pbb[kh * 3 + kw] * val;
                    }
            }
            #pragma unroll
            for (int m = 1; m < 16; m <<= 1) {
                s0 += __shfl_xor_sync(0xffffffffu, s0, m);
                pb += __shfl_xor_sync(0xffffffffu, pb, m);
                mn = fminf(mn, __shfl_xor_sync(0xffffffffu, mn, m));
                mx = fmaxf(mx, __shfl_xor_sync(0xffffffffu, mx, m));
            }
            const float mu  = s0 * (1.f / 288.f);
            const float rng = mx - mn + 1e-6f;
            const float s15 = __fdiv_rn(15.f, rng);
            float sd2 = 0.f;
            unsigned long long hl = 0ull, hh = 0ull;
            #pragma unroll
            for (int i = 0; i < 18; i++) {
                float d = v[i] - mu;
                sd2 += d * d;
                float dmn = v[i] - mn;
                float y = dmn * s15;
                int b = (int)y;
                float fb = (float)b;
                float eps = y * 1.2e-6f + 1e-35f;
                if (y - fb < eps || (fb + 1.0f) - y < eps)
                    b = (int)(__fdiv_rn(dmn, rng) * 15.0f);   // exact reference path
                b = min(b, 15);
                unsigned long long one = 1ull << ((b & 7) * 8);
                hl += (b < 8) ? one : 0ull;
                hh += (b < 8) ? 0ull : one;
            }
            #pragma unroll
            for (int m = 1; m < 16; m <<= 1) sd2 += __shfl_xor_sync(0xffffffffu, sd2, m);
            const float var   = sd2 * (1.f / 288.f);
            const float sigma = __fsqrt_rn(var + 1e-6f);
            const float zinv  = __fdiv_rn(1.f, sigma + 1e-6f);
            float s3 = 0.f, s4 = 0.f;
            #pragma unroll
            for (int i = 0; i < 18; i++) {
                float z = (v[i] - mu) * zinv, z2 = z * z;
                s3 += z2 * z;
                s4 += z2 * z2;
            }
            const unsigned long long M8 = 0x00FF00FF00FF00FFull;
            unsigned long long wl0 = hl & M8, wl1 = (hl >> 8) & M8;
            unsigned long long wh0 = hh & M8, wh1 = (hh >> 8) & M8;
            #pragma unroll
            for (int m = 1; m < 16; m <<= 1) {
                s3  += __shfl_xor_sync(0xffffffffu, s3, m);
                s4  += __shfl_xor_sync(0xffffffffu, s4, m);
                wl0 += __shfl_xor_sync(0xffffffffu, wl0, m);
                wl1 += __shfl_xor_sync(0xffffffffu, wl1, m);
                wh0 += __shfl_xor_sync(0xffffffffu, wh0, m);
                wh1 += __shfl_xor_sync(0xffffffffu, wh1, m);
            }
            // entropy: bin "sub" on each lane
            unsigned long long wsel = (sub < 8) ? ((sub & 1) ? wl1 : wl0)
                                                : ((sub & 1) ? wh1 : wh0);
            unsigned cnt = (unsigned)(wsel >> (((sub >> 1) & 3) * 16)) & 0xFFFFu;
            float p = (float)cnt * (1.f / 288.f);
            float ent = -p * __logf(p + 1e-9f);
            #pragma unroll
            for (int m = 1; m < 16; m <<= 1) ent += __shfl_xor_sync(0xffffffffu, ent, m);
            if (sub == 0) {
                sm[O_ST + pxl * 8 + 0] = mu;
                sm[O_ST + pxl * 8 + 1] = sigma;
                sm[O_ST + pxl * 8 + 2] = s3 * (1.f / 288.f);
                sm[O_ST + pxl * 8 + 3] = s4 * (1.f / 288.f) - 3.0f;
                sm[O_ST + pxl * 8 + 4] = ent;
                sm[O_PBV + pxl] = pb;
            }
        }
    }
    __syncthreads();

    // ---------------- Phase B: h = relu(fc1(s)), 4 thr/px ----------------
    {
        const int px = t >> 2, d0 = (t & 3) * 16;
        const float s0 = sm[O_ST + px * 8 + 0], s1 = sm[O_ST + px * 8 + 1],
                    s2 = sm[O_ST + px * 8 + 2], s3 = sm[O_ST + px * 8 + 3],
                    s4 = sm[O_ST + px * 8 + 4];
        #pragma unroll 4
        for (int dd = 0; dd < 16; dd++) {
            int d = d0 + dd;
            const float* wp = sm + O_FC1W + d * 5;
            float a = sm[O_FC1B + d] + s0 * wp[0] + s1 * wp[1] + s2 * wp[2]
                      + s3 * wp[3] + s4 * wp[4];
            sm[O_HS + px * HS_ST + d] = fmaxf(a, 0.f);
        }
    }

    // ---------------- Phase C: q-GEMM 64px x 64d x 288k, d-pair f32x2, no MOVs ----------------
    const int dg = t & 15, pg = t >> 4;
    const int d0 = dg * 4;                 // 4 d = 2 pairs
    const int rr = pg >> 3, cpg = pg & 7;  // 4 px = cols cpg*4..+3, row rr
    unsigned long long acc[2][4];
    #pragma unroll
    for (int q = 0; q < 2; q++)
        #pragma unroll
        for (int p = 0; p < 4; p++) acc[q][p] = 0ull;

    #pragma unroll 1
    for (int seg = 0; seg < 8; seg++) {
        __syncthreads();
        {   // stage phi k-rows [seg*36, seg*36+36)
            const float4* pw4 = (const float4*)phi_w;
            float4* ps4 = (float4*)(sm + O_PHI);
            #pragma unroll
            for (int i = 0; i < 3; i++) {
                int idx = t + i * NT;
                if (idx < 576) ps4[idx] = pw4[seg * 576 + idx];
            }
        }
        __syncthreads();
        #pragma unroll 1
        for (int cl = 0; cl < 4; cl++) {
            const int c = seg * 4 + cl;
            #pragma unroll
            for (int kh = 0; kh < 3; kh++) {
                const float* ab = sm + O_XS + c * XS_CST + (rr + kh) * XS_RST + cpg * 8;
                const ulonglong2 sA = *(const ulonglong2*)ab;
                const ulonglong2 sB = *(const ulonglong2*)(ab + 4);
                const ulonglong2 sC = *(const ulonglong2*)(ab + 8);
                unsigned long long seg64[6] = {sA.x, sA.y, sB.x, sB.y, sC.x, sC.y};
                #pragma unroll
                for (int kw = 0; kw < 3; kw++) {
                    const ulonglong2 b = *(const ulonglong2*)
                        (sm + O_PHI + (cl * 9 + kh * 3 + kw) * 64 + d0);
                    FMA2(acc[0][0], seg64[kw + 0], b.x);
                    FMA2(acc[0][1], seg64[kw + 1], b.x);
                    FMA2(acc[0][2], seg64[kw + 2], b.x);
                    FMA2(acc[0][3], seg64[kw + 3], b.x);
                    FMA2(acc[1][0], seg64[kw + 0], b.y);
                    FMA2(acc[1][1], seg64[kw + 1], b.y);
                    FMA2(acc[1][2], seg64[kw + 2], b.y);
                    FMA2(acc[1][3], seg64[kw + 3], b.y);
                }
            }
        }
    }
    // epilogue: proj = h.q + phi_b.patch (f32x2 dot, 16-lane reduce)
    {
        #pragma unroll
        for (int p = 0; p < 4; p++) {
            const int pxl = rr * 32 + cpg * 4 + p;
            const unsigned long long h0 = *(const unsigned long long*)
                (sm + O_HS + pxl * HS_ST + d0);
            const unsigned long long h1 = *(const unsigned long long*)
                (sm + O_HS + pxl * HS_ST + d0 + 2);
            unsigned long long s = 0ull;
            FMA2(s, acc[0][p], h0);
            FMA2(s, acc[1][p], h1);
            unsigned lo, hi;
            UPK2(lo, hi, s);
            float part = __uint_as_float(lo) + __uint_as_float(hi);
            #pragma unroll
            for (int m = 1; m < 16; m <<= 1)
                part += __shfl_xor_sync(0xffffffffu, part, m);
            if (dg == 0) sm[O_PROJ + pxl] = part + sm[O_PBV + pxl];
        }
    }
    __syncthreads();

    // stage alpha_w^T into dead xs_dup area (stride 68)
    for (int idx = t; idx < 64 * 64; idx += NT) {
        int c = idx >> 6, d = idx & 63;
        sm[d * 68 + c] = alpha_w[idx];
    }
    __syncthreads();

    // ---------------- Phase D: alpha GEMV (c-pair f32x2) + BN + SiLU ----------------
    {
        const int px = t >> 2, cq = t & 3;
        const int c0 = cq * 16;                    // 16 c = 8 pairs
        unsigned long long ac[8];
        #pragma unroll
        for (int i = 0; i < 8; i++) ac[i] = 0ull;
        #pragma unroll 4
        for (int d = 0; d < 64; d++) {
            float h = sm[O_HS + px * HS_ST + d];
            unsigned long long hd;
            PK2(hd, __float_as_uint(h), __float_as_uint(h));
            const float* wb = sm + d * 68 + c0;
            const ulonglong2 w0 = *(const ulonglong2*)wb;
            const ulonglong2 w1 = *(const ulonglong2*)(wb + 4);
            const ulonglong2 w2 = *(const ulonglong2*)(wb + 8);
            const ulonglong2 w3 = *(const ulonglong2*)(wb + 12);
            FMA2(ac[0], hd, w0.x); FMA2(ac[1], hd, w0.y);
            FMA2(ac[2], hd, w1.x); FMA2(ac[3], hd, w1.y);
            FMA2(ac[4], hd, w2.x); FMA2(ac[5], hd, w2.y);
            FMA2(ac[6], hd, w3.x); FMA2(ac[7], hd, w3.y);
        }
        const float prj = sm[O_PROJ + px];
        const int row  = it * 2 + (px >> 5);
        const int gcol = j0 + (px & 31);
        #pragma unroll
        for (int i = 0; i < 8; i++) {
            unsigned u0, u1;
            UPK2(u0, u1, ac[i]);
            #pragma unroll
            for (int s2 = 0; s2 < 2; s2++) {
                const int c = c0 + 2 * i + s2;
                float al = __uint_as_float(s2 ? u1 : u0) + sm[O_ALB + c];
                float y  = (al * prj - sm[O_BNM + c]) * sm[O_BNI + c] + sm[O_BNB + c];
                float r  = y * __fdividef(1.f, 1.f + __expf(-y));
                out[((bz * 64 + c) * IMG + row) * IMG + gcol] = r;
            }
        }
    }
}

extern "C" void kernel_launch(void* const* d_in, const int* in_sizes, int n_in,
                              void* d_out, int out_size) {
    cudaFuncSetAttribute(sac_kernel, cudaFuncAttributeMaxDynamicSharedMemorySize,
                         SMEM_F * sizeof(float));
    dim3 grid(3, 48, 4);
    sac_kernel<<<grid, NT, SMEM_F * sizeof(float)>>>(
        (const float*)d_in[0],  (const float*)d_in[1], (const float*)d_in[2],
        (const float*)d_in[3],  (const float*)d_in[4], (const float*)d_in[5],
        (const float*)d_in[6],  (const float*)d_in[7], (const float*)d_in[8],
        (const float*)d_in[9],  (const float*)d_in[10], (float*)d_out);
}

// round 8
// speedup vs baseline: 1.3739x; 1.3739x over previous
#include <cuda_runtime.h>
#include <math.h>

#define IMG 96
#define NT  256

// ---- smem layout (float word offsets) ----
#define O_XS    0                 // xs_dup: 32ch x 6 rows x 34 dup-cols(float2)
#define XS_CST  436               // 436 mod 32 = 20 -> <=2-way conflicts; 16B-aligned
#define XS_RST  68
#define O_PHI   13952             // phi chunk: 72 k-rows x 64 d (also alphaT later)
#define O_HS    18560             // h: 128 px x 66
#define HS_ST   66
#define O_ST    27008             // stats: 128 x 6 ([5] = phi_b dot patch)
#define O_PROJ  27776
#define O_FC1W  27904
#define O_FC1B  28224
#define O_PHIB  28288
#define O_ALB   28576
#define O_BNI   28640
#define O_BNM   28704
#define O_BNB   28768
#define SMEM_F  28832             // 115328 B -> 2 blocks/SM

#define PK2(d, lo, hi) asm("mov.b64 %0, {%1, %2};" : "=l"(d) : "r"(lo), "r"(hi))
#define UPK2(lo, hi, v) asm("mov.b64 {%0, %1}, %2;" : "=r"(lo), "=r"(hi) : "l"(v))
#define FMA2(d, a, b) asm("fma.rn.f32x2 %0, %1, %2, %3;" : "=l"(d) : "l"(a), "l"(b), "l"(d))

__global__ __launch_bounds__(NT, 2) void sac_kernel(
    const float* __restrict__ x,       const float* __restrict__ fc1_w,
    const float* __restrict__ fc1_b,   const float* __restrict__ alpha_w,
    const float* __restrict__ alpha_b, const float* __restrict__ phi_w,
    const float* __restrict__ phi_b,   const float* __restrict__ bn_g,
    const float* __restrict__ bn_b,    const float* __restrict__ bn_m,
    const float* __restrict__ bn_v,    float* __restrict__ out)
{
    extern __shared__ float sm[];
    const int t  = threadIdx.x;
    const int jt = blockIdx.x;          // 3 col tiles of 32
    const int it = blockIdx.y;          // 24 row tiles of 4
    const int bz = blockIdx.z;
    const int j0 = jt * 32;

    // ---------------- Phase 0: stage ----------------
    for (int idx = t; idx < 32 * 204; idx += NT) {     // 6 rows x 34 cols per ch
        int c = idx / 204, rem = idx - c * 204;
        int r = rem / 34,  cc = rem - r * 34;
        int gr = it * 4 - 1 + r, gc = j0 - 1 + cc;
        float v = 0.f;
        if ((unsigned)gr < IMG && (unsigned)gc < IMG)
            v = x[((bz * 32 + c) * IMG + gr) * IMG + gc];
        *(float2*)(sm + O_XS + c * XS_CST + r * XS_RST + cc * 2) = make_float2(v, v);
    }
    for (int idx = t; idx < 320; idx += NT) sm[O_FC1W + idx] = fc1_w[idx];
    for (int idx = t; idx < 288; idx += NT) sm[O_PHIB + idx] = phi_b[idx];
    if (t < 64) {
        sm[O_FC1B + t] = fc1_b[t];
        sm[O_ALB  + t] = alpha_b[t];
        sm[O_BNI  + t] = bn_g[t] * rsqrtf(bn_v[t] + 1e-5f);
        sm[O_BNM  + t] = bn_m[t];
        sm[O_BNB  + t] = bn_b[t];
    }
    __syncthreads();

    // ---------------- Phase A: stats, 8 thr/px, 4 passes of 32 px ----------------
    {
        const int sub = t & 7;
        #pragma unroll 1
        for (int p4 = 0; p4 < 4; p4++) {
            const int pxl = p4 * 32 + (t >> 3);
            const int rr = pxl >> 5, ca = pxl & 31;
            float v[36];
            float s0 = 0.f, mn = 3.4e38f, mx = -3.4e38f, pb = 0.f;
            #pragma unroll
            for (int cc = 0; cc < 4; cc++) {
                const int c = sub + cc * 8;
                const float* xb = sm + O_XS + c * XS_CST + rr * XS_RST + ca * 2;
                const float* pbb = sm + O_PHIB + c * 9;
                #pragma unroll
                for (int kh = 0; kh < 3; kh++)
                    #pragma unroll
                    for (int kw = 0; kw < 3; kw++) {
                        float val = xb[kh * XS_RST + kw * 2];
                        v[cc * 9 + kh * 3 + kw] = val;
                        s0 += val;
                        mn = fminf(mn, val);
                        mx = fmaxf(mx, val);
                        pb += pbb[kh * 3 + kw] * val;
                    }
            }
            #pragma unroll
            for (int m = 1; m < 8; m <<= 1) {
                s0 += __shfl_xor_sync(0xffffffffu, s0, m);
                pb += __shfl_xor_sync(0xffffffffu, pb, m);
                mn = fminf(mn, __shfl_xor_sync(0xffffffffu, mn, m));
                mx = fmaxf(mx, __shfl_xor_sync(0xffffffffu, mx, m));
            }
            const float mu  = s0 * (1.f / 288.f);
            const float rng = mx - mn + 1e-6f;
            const float s15 = __fdiv_rn(15.f, rng);
            float sd2 = 0.f;
            unsigned long long hl = 0ull, hh = 0ull;
            #pragma unroll
            for (int i = 0; i < 36; i++) {
                float d = v[i] - mu;
                sd2 += d * d;
                float dmn = v[i] - mn;
                float y = dmn * s15;
                int b = (int)y;
                float fb = (float)b;
                float eps = y * 1.2e-6f + 1e-35f;
                if (y - fb < eps || (fb + 1.0f) - y < eps)
                    b = (int)(__fdiv_rn(dmn, rng) * 15.0f);   // exact reference path
                b = min(b, 15);
                unsigned long long one = 1ull << ((b & 7) * 8);
                hl += (b < 8) ? one : 0ull;
                hh += (b < 8) ? 0ull : one;
            }
            #pragma unroll
            for (int m = 1; m < 8; m <<= 1) sd2 += __shfl_xor_sync(0xffffffffu, sd2, m);
            const float var   = sd2 * (1.f / 288.f);
            const float sigma = __fsqrt_rn(var + 1e-6f);
            const float zinv  = __fdiv_rn(1.f, sigma + 1e-6f);
            float s3 = 0.f, s4 = 0.f;
            #pragma unroll
            for (int i = 0; i < 36; i++) {
                float z = (v[i] - mu) * zinv, z2 = z * z;
                s3 += z2 * z;
                s4 += z2 * z2;
            }
            const unsigned long long M8 = 0x00FF00FF00FF00FFull;
            unsigned long long wl0 = hl & M8, wl1 = (hl >> 8) & M8;
            unsigned long long wh0 = hh & M8, wh1 = (hh >> 8) & M8;
            #pragma unroll
            for (int m = 1; m < 8; m <<= 1) {
                s3  += __shfl_xor_sync(0xffffffffu, s3, m);
                s4  += __shfl_xor_sync(0xffffffffu, s4, m);
                wl0 += __shfl_xor_sync(0xffffffffu, wl0, m);
                wl1 += __shfl_xor_sync(0xffffffffu, wl1, m);
                wh0 += __shfl_xor_sync(0xffffffffu, wh0, m);
                wh1 += __shfl_xor_sync(0xffffffffu, wh1, m);
            }
            // entropy: 2 bins per lane
            unsigned long long wa = (sub & 2) ? wl1 : wl0;
            unsigned long long wb = (sub & 2) ? wh1 : wh0;
            unsigned long long w  = (sub & 4) ? wb : wa;
            unsigned c0 = (unsigned)(w >> ((sub & 1) * 32)) & 0xFFFFu;
            unsigned c1 = (unsigned)(w >> ((sub & 1) * 32 + 16)) & 0xFFFFu;
            float p0 = (float)c0 * (1.f / 288.f), p1 = (float)c1 * (1.f / 288.f);
            float ent = -(p0 * __logf(p0 + 1e-9f) + p1 * __logf(p1 + 1e-9f));
            #pragma unroll
            for (int m = 1; m < 8; m <<= 1) ent += __shfl_xor_sync(0xffffffffu, ent, m);
            if (sub == 0) {
                sm[O_ST + pxl * 6 + 0] = mu;
                sm[O_ST + pxl * 6 + 1] = sigma;
                sm[O_ST + pxl * 6 + 2] = s3 * (1.f / 288.f);
                sm[O_ST + pxl * 6 + 3] = s4 * (1.f / 288.f) - 3.0f;
                sm[O_ST + pxl * 6 + 4] = ent;
                sm[O_ST + pxl * 6 + 5] = pb;
            }
        }
    }
    __syncthreads();

    // ---------------- Phase B: h = relu(fc1(s)), 2 thr/px ----------------
    {
        const int px = t >> 1, d0 = (t & 1) * 32;
        const float s0 = sm[O_ST + px * 6 + 0], s1 = sm[O_ST + px * 6 + 1],
                    s2 = sm[O_ST + px * 6 + 2], s3 = sm[O_ST + px * 6 + 3],
                    s4 = sm[O_ST + px * 6 + 4];
        #pragma unroll 8
        for (int dd = 0; dd < 32; dd++) {
            int d = d0 + dd;
            const float* wp = sm + O_FC1W + d * 5;
            float a = sm[O_FC1B + d] + s0 * wp[0] + s1 * wp[1] + s2 * wp[2]
                      + s3 * wp[3] + s4 * wp[4];
            sm[O_HS + px * HS_ST + d] = fmaxf(a, 0.f);
        }
    }

    // ---------------- Phase C: q-GEMM 128px x 64d x 288k, zero-MOV f32x2 ----------------
    const int dg = t & 15, pg = t >> 4;
    const int d0 = dg * 4;                 // 4 d = 2 pairs
    const int rr = pg >> 2, cpg = pg & 3;  // 8 px: cols cpg*8..+7, row rr
    unsigned long long acc[2][8];
    #pragma unroll
    for (int q = 0; q < 2; q++)
        #pragma unroll
        for (int p = 0; p < 8; p++) acc[q][p] = 0ull;

    #pragma unroll 1
    for (int seg = 0; seg < 4; seg++) {
        __syncthreads();
        {   // stage phi k-rows [seg*72, seg*72+72)
            const float4* pw4 = (const float4*)phi_w;
            float4* ps4 = (float4*)(sm + O_PHI);
            #pragma unroll
            for (int i = 0; i < 5; i++) {
                int idx = t + i * NT;
                if (idx < 1152) ps4[idx] = pw4[seg * 1152 + idx];
            }
        }
        __syncthreads();
        #pragma unroll 1
        for (int cl = 0; cl < 8; cl++) {
            const int c = seg * 8 + cl;
            #pragma unroll
            for (int kh = 0; kh < 3; kh++) {
                const float* ab = sm + O_XS + c * XS_CST + (rr + kh) * XS_RST + cpg * 16;
                const ulonglong2 sA = *(const ulonglong2*)ab;
                const ulonglong2 sB = *(const ulonglong2*)(ab + 4);
                const ulonglong2 sC = *(const ulonglong2*)(ab + 8);
                const ulonglong2 sD = *(const ulonglong2*)(ab + 12);
                const ulonglong2 sE = *(const ulonglong2*)(ab + 16);
                unsigned long long seg64[10] = {sA.x, sA.y, sB.x, sB.y, sC.x,
                                                sC.y, sD.x, sD.y, sE.x, sE.y};
                #pragma unroll
                for (int kw = 0; kw < 3; kw++) {
                    const ulonglong2 b = *(const ulonglong2*)
                        (sm + O_PHI + (cl * 9 + kh * 3 + kw) * 64 + d0);
                    #pragma unroll
                    for (int p = 0; p < 8; p++) {
                        FMA2(acc[0][p], seg64[p + kw], b.x);
                        FMA2(acc[1][p], seg64[p + kw], b.y);
                    }
                }
            }
        }
    }
    // epilogue: proj = h.q + phi_b.patch (f32x2 dot, 16-lane reduce)
    {
        #pragma unroll
        for (int p = 0; p < 8; p++) {
            const int pxl = rr * 32 + cpg * 8 + p;
            const unsigned long long h0 = *(const unsigned long long*)
                (sm + O_HS + pxl * HS_ST + d0);
            const unsigned long long h1 = *(const unsigned long long*)
                (sm + O_HS + pxl * HS_ST + d0 + 2);
            unsigned long long s = 0ull;
            FMA2(s, acc[0][p], h0);
            FMA2(s, acc[1][p], h1);
            unsigned lo, hi;
            UPK2(lo, hi, s);
            float part = __uint_as_float(lo) + __uint_as_float(hi);
            #pragma unroll
            for (int m = 1; m < 16; m <<= 1)
                part += __shfl_xor_sync(0xffffffffu, part, m);
            if (dg == 0) sm[O_PROJ + pxl] = part + sm[O_ST + pxl * 6 + 5];
        }
    }
    __syncthreads();

    // stage alpha_w^T into dead phi area (stride 68)
    for (int idx = t; idx < 64 * 64; idx += NT) {
        int c = idx >> 6, d = idx & 63;
        sm[O_PHI + d * 68 + c] = alpha_w[idx];
    }
    __syncthreads();

    // ---------------- Phase D: alpha GEMV (c-pair f32x2) + BN + SiLU ----------------
    {
        const int px = t >> 1, cq = t & 1;
        const int c0 = cq * 32;                    // 32 c = 16 pairs
        unsigned long long ac[16];
        #pragma unroll
        for (int i = 0; i < 16; i++) ac[i] = 0ull;
        #pragma unroll 4
        for (int d = 0; d < 64; d++) {
            float h = sm[O_HS + px * HS_ST + d];
            unsigned long long hd;
            PK2(hd, __float_as_uint(h), __float_as_uint(h));
            const float* wb = sm + O_PHI + d * 68 + c0;
            #pragma unroll
            for (int i = 0; i < 8; i++) {
                const ulonglong2 w = *(const ulonglong2*)(wb + i * 4);
                FMA2(ac[2 * i + 0], hd, w.x);
                FMA2(ac[2 * i + 1], hd, w.y);
            }
        }
        const float prj = sm[O_PROJ + px];
        const int row  = it * 4 + (px >> 5);
        const int gcol = j0 + (px & 31);
        #pragma unroll
        for (int i = 0; i < 16; i++) {
            unsigned u0, u1;
            UPK2(u0, u1, ac[i]);
            #pragma unroll
            for (int s2 = 0; s2 < 2; s2++) {
                const int c = c0 + 2 * i + s2;
                float al = __uint_as_float(s2 ? u1 : u0) + sm[O_ALB + c];
                float y  = (al * prj - sm[O_BNM + c]) * sm[O_BNI + c] + sm[O_BNB + c];
                float r  = y * __fdividef(1.f, 1.f + __expf(-y));
                out[((bz * 64 + c) * IMG + row) * IMG + gcol] = r;
            }
        }
    }
}

extern "C" void kernel_launch(void* const* d_in, const int* in_sizes, int n_in,
                              void* d_out, int out_size) {
    cudaFuncSetAttribute(sac_kernel, cudaFuncAttributeMaxDynamicSharedMemorySize,
                         SMEM_F * sizeof(float));
    dim3 grid(3, 24, 4);
    sac_kernel<<<grid, NT, SMEM_F * sizeof(float)>>>(
        (const float*)d_in[0],  (const float*)d_in[1], (const float*)d_in[2],
        (const float*)d_in[3],  (const float*)d_in[4], (const float*)d_in[5],
        (const float*)d_in[6],  (const float*)d_in[7], (const float*)d_in[8],
        (const float*)d_in[9],  (const float*)d_in[10], (float*)d_out);
}